// round 8
// baseline (speedup 1.0000x reference)
#include <cuda_runtime.h>
#include <cstdint>

#define BB 4
#define CC 512
#define KK 64
#define NN 1024
#define GRID 256
#define NTB 16   // phase B n-tile

typedef unsigned long long ull;

// ---- scratch (static __device__, no allocations) ----
__device__ __align__(16) float g_inv[KK * CC];    // [k][c]
__device__ __align__(16) float g_inv2t[CC * KK];  // [c][k]
__device__ __align__(16) float g_m2t[CC * KK];    // [c][k]
__device__ __align__(16) float g_ck[KK];
__device__ __align__(16) float g_wpart[(NN / NTB) * BB * KK];  // [(b*64+nb)*KK+k]
__device__ __align__(16) float g_part[8 * BB * KK * CC];       // 8 n-splits
__device__ unsigned g_bar_count = 0;
__device__ unsigned g_bar_gen = 0;

// ---- f32x2 helpers ----
__device__ __forceinline__ ull pack2(float x, float y) {
    ull r; asm("mov.b64 %0, {%1,%2};" : "=l"(r) : "f"(x), "f"(y)); return r;
}
__device__ __forceinline__ ull fma2(ull a, ull b, ull c) {
    ull d; asm("fma.rn.f32x2 %0, %1, %2, %3;" : "=l"(d) : "l"(a), "l"(b), "l"(c)); return d;
}
__device__ __forceinline__ ull mul2(ull a, ull b) {
    ull d; asm("mul.rn.f32x2 %0, %1, %2;" : "=l"(d) : "l"(a), "l"(b)); return d;
}
__device__ __forceinline__ float2 unpack2(ull v) {
    float2 f; asm("mov.b64 {%0,%1}, %2;" : "=f"(f.x), "=f"(f.y) : "l"(v)); return f;
}

// ---- cp.async helpers ----
__device__ __forceinline__ void cp_async16(void* smem_dst, const void* gsrc) {
    unsigned sa = (unsigned)__cvta_generic_to_shared(smem_dst);
    asm volatile("cp.async.cg.shared.global [%0], [%1], 16;\n" :: "r"(sa), "l"(gsrc));
}
__device__ __forceinline__ void cp_commit() { asm volatile("cp.async.commit_group;\n"); }
template <int N>
__device__ __forceinline__ void cp_wait() { asm volatile("cp.async.wait_group %0;\n" :: "n"(N)); }

// ---- grid-wide sense-reversing barrier (all GRID blocks resident) ----
__device__ __forceinline__ void grid_bar() {
    __threadfence();
    __syncthreads();
    if (threadIdx.x == 0) {
        unsigned gen = *(volatile unsigned*)&g_bar_gen;
        if (atomicAdd(&g_bar_count, 1u) == GRID - 1) {
            g_bar_count = 0;
            __threadfence();
            *(volatile unsigned*)&g_bar_gen = gen + 1;
        } else {
            while (*(volatile unsigned*)&g_bar_gen == gen) { __nanosleep(32); }
        }
        __threadfence();
    }
    __syncthreads();
}

// ------------------------------------------------------------------
__global__ __launch_bounds__(256, 2) void fused_all(const float* __restrict__ x,
                                                    const float* __restrict__ anchor,
                                                    const float* __restrict__ sp,
                                                    float* __restrict__ nodes_out,
                                                    float* __restrict__ soft_out) {
    __shared__ __align__(16) unsigned char SMEM[34048];
    const int tid = threadIdx.x;
    const int blk = blockIdx.x;

    // ========== Phase A: prep (blocks 0..15, 4 k-rows each) ==========
    if (blk < 16) {
        float* smI2 = (float*)SMEM;                 // 4*512
        float* smM2 = smI2 + 4 * 512;               // 4*512
        float* ckred = smM2 + 4 * 512;              // 8*4
        const int k0 = blk * 4;
        const int lane = tid & 31, wid = tid >> 5;
        float ck4[4] = {0.f, 0.f, 0.f, 0.f};
#pragma unroll
        for (int kl = 0; kl < 4; kl++) {
#pragma unroll
            for (int h = 0; h < 2; h++) {
                const int c = tid + h * 256;
                const int gi = (k0 + kl) * CC + c;
                const float s = 1.f / (1.f + __expf(-sp[gi]));
                const float inv = __fdividef(1.f, s + 1e-7f);
                const float inv2 = inv * inv;
                const float a = anchor[gi];
                g_inv[gi] = inv;
                smI2[kl * 512 + c] = inv2;
                smM2[kl * 512 + c] = -2.f * a * inv2;
                ck4[kl] += a * a * inv2;
            }
        }
#pragma unroll
        for (int kl = 0; kl < 4; kl++) {
            float v = ck4[kl];
#pragma unroll
            for (int o = 16; o > 0; o >>= 1) v += __shfl_xor_sync(0xffffffffu, v, o);
            if (lane == 0) ckred[wid * 4 + kl] = v;
        }
        __syncthreads();
        if (tid < 4) {
            float s = 0.f;
#pragma unroll
            for (int w = 0; w < 8; w++) s += ckred[w * 4 + tid];
            g_ck[k0 + tid] = s;
        }
#pragma unroll
        for (int h = 0; h < 2; h++) {
            const int c = tid + h * 256;
            float4 v = make_float4(smI2[c], smI2[512 + c], smI2[1024 + c], smI2[1536 + c]);
            *reinterpret_cast<float4*>(&g_inv2t[c * KK + k0]) = v;
            float4 v2 = make_float4(smM2[c], smM2[512 + c], smM2[1024 + c], smM2[1536 + c]);
            *reinterpret_cast<float4*>(&g_m2t[c * KK + k0]) = v2;
        }
    }
    grid_bar();

    // ========== Phase B: d2 GEMM (64k x 16n) + softmax, 256 items ==========
    {
        float* Wst = (float*)SMEM;      // 3 * 1024
        float* Mst = Wst + 3072;        // 3 * 1024
        float* Xst = Mst + 3072;        // 3 * 256
        float* S = Xst + 768;           // 64*17
        float* pm = S + 1088;           // 256
        float* ps = pm + 256;           // 256
        const int b = blk & 3;
        const int nb = blk >> 2;        // 0..63
        const int n0 = nb * NTB;
        const int tk = tid >> 4;        // 0..15 -> k base tk*4
        const int tn = tid & 15;        // 0..15 -> 1 n column
        const float* xb = x + (size_t)b * CC * NN;

        auto issueB = [&](int chunk, int buf) {
            const int c0 = chunk * 16;
            cp_async16(&Wst[buf * 1024 + tid * 4], g_inv2t + c0 * KK + tid * 4);
            cp_async16(&Mst[buf * 1024 + tid * 4], g_m2t + c0 * KK + tid * 4);
            if (tid < 64) {
                const int cc = tid >> 2, nn4 = (tid & 3) * 4;
                cp_async16(&Xst[buf * 256 + cc * NTB + nn4],
                           xb + (size_t)(c0 + cc) * NN + n0 + nn4);
            }
            cp_commit();
        };

        ull accq0 = 0ull, accq1 = 0ull, accl0 = 0ull, accl1 = 0ull;

        issueB(0, 0);
        issueB(1, 1);
        for (int ch = 0; ch < 32; ch++) {
            cp_wait<1>();
            __syncthreads();
            const int buf = ch - (ch / 3) * 3;  // ch % 3
            const float* Wb = Wst + buf * 1024;
            const float* Mb = Mst + buf * 1024;
            const float* Xb = Xst + buf * 256;
#pragma unroll
            for (int cc = 0; cc < 16; cc++) {
                const ulonglong2 wp = *reinterpret_cast<const ulonglong2*>(Wb + cc * 64 + tk * 4);
                const ulonglong2 mp = *reinterpret_cast<const ulonglong2*>(Mb + cc * 64 + tk * 4);
                const float xv = Xb[cc * NTB + tn];
                const ull xd = pack2(xv, xv);
                const ull xx = mul2(xd, xd);
                accq0 = fma2(wp.x, xx, accq0);
                accq1 = fma2(wp.y, xx, accq1);
                accl0 = fma2(mp.x, xd, accl0);
                accl1 = fma2(mp.y, xd, accl1);
            }
            if (ch + 2 < 32) {
                const int nbuf = (ch + 2) - ((ch + 2) / 3) * 3;
                issueB(ch + 2, nbuf);
            }
        }

        // logits -> S (stride 17)
        {
            const int k0 = tk * 4;
            const float2 q0 = unpack2(accq0), q1 = unpack2(accq1);
            const float2 l0 = unpack2(accl0), l1 = unpack2(accl1);
            S[(k0 + 0) * 17 + tn] = -0.5f * (q0.x + l0.x + g_ck[k0 + 0]);
            S[(k0 + 1) * 17 + tn] = -0.5f * (q0.y + l0.y + g_ck[k0 + 1]);
            S[(k0 + 2) * 17 + tn] = -0.5f * (q1.x + l1.x + g_ck[k0 + 2]);
            S[(k0 + 3) * 17 + tn] = -0.5f * (q1.y + l1.y + g_ck[k0 + 3]);
        }
        __syncthreads();

        // parallel softmax: kg = tid>>4 owns 4 k, column n = tid&15
        {
            const int n = tid & 15;
            const int kg = tid >> 4;  // 0..15
            const int kb = kg * 4;
            float v[4];
#pragma unroll
            for (int i = 0; i < 4; i++) v[i] = S[(kb + i) * 17 + n];
            float m4 = fmaxf(fmaxf(v[0], v[1]), fmaxf(v[2], v[3]));
            pm[kg * 16 + n] = m4;
            __syncthreads();
            float m = pm[n];
#pragma unroll
            for (int j = 1; j < 16; j++) m = fmaxf(m, pm[j * 16 + n]);
            float e[4];
            float es = 0.f;
#pragma unroll
            for (int i = 0; i < 4; i++) { e[i] = __expf(v[i] - m); es += e[i]; }
            ps[kg * 16 + n] = es;
            __syncthreads();
            float s = ps[n];
#pragma unroll
            for (int j = 1; j < 16; j++) s += ps[j * 16 + n];
            const float invs = 1.f / s;
            float* outp = soft_out + (size_t)b * KK * NN + n0 + n;
#pragma unroll
            for (int i = 0; i < 4; i++) {
                const float p = e[i] * invs;
                S[(kb + i) * 17 + n] = p;
                outp[(size_t)(kb + i) * NN] = p;
            }
        }
        __syncthreads();

        // per-item wsum partials (threads 0..63, one per k)
        if (tid < 64) {
            float s = 0.f;
#pragma unroll
            for (int n = 0; n < NTB; n++) s += S[tid * 17 + n];
            g_wpart[(b * 64 + nb) * KK + tid] = s;
        }
    }
    grid_bar();

    // ========== Phase C: num GEMM, 256 items (8c x 4b x 8 n-splits) ==========
    {
        float* As = (float*)SMEM;         // 2 * 16*68
        float* Xs = As + 2 * 1088;        // 2 * 16*68
        const int ct = blk & 7;
        const int b = (blk >> 3) & 3;
        const int ns = blk >> 5;          // 0..7
        const int c0 = ct * 64;
        const int nbeg = ns * (NN / 8);
        const int tc = tid & 15;
        const int tk = tid >> 4;

        ull acc2[4][2];
#pragma unroll
        for (int i = 0; i < 4; i++) { acc2[i][0] = 0ull; acc2[i][1] = 0ull; }

        const float* Ab = soft_out + (size_t)b * KK * NN;
        const float* xb = x + (size_t)b * CC * NN;

        const int row = tid >> 4;          // base row for r-loop
        const int nn = tid & 15;

        // prologue: load+store iter 0
        {
            const int n0 = nbeg;
#pragma unroll
            for (int r = 0; r < 4; r++) {
                const int rw = row + r * 16;
                As[nn * 68 + rw] = Ab[(size_t)rw * NN + n0 + nn];
                Xs[nn * 68 + rw] = xb[(size_t)(c0 + rw) * NN + n0 + nn];
            }
        }
        for (int it = 0; it < 8; it++) {
            float aR[4], xR[4];
            if (it + 1 < 8) {
                const int n0 = nbeg + (it + 1) * 16;
#pragma unroll
                for (int r = 0; r < 4; r++) {
                    const int rw = row + r * 16;
                    aR[r] = Ab[(size_t)rw * NN + n0 + nn];
                    xR[r] = xb[(size_t)(c0 + rw) * NN + n0 + nn];
                }
            }
            __syncthreads();
            const float* Ac = As + (it & 1) * 1088;
            const float* Xc = Xs + (it & 1) * 1088;
#pragma unroll
            for (int q = 0; q < 16; q++) {
                const float4 a4 = *reinterpret_cast<const float4*>(&Ac[q * 68 + tk * 4]);
                const ull ad0 = pack2(a4.x, a4.x);
                const ull ad1 = pack2(a4.y, a4.y);
                const ull ad2 = pack2(a4.z, a4.z);
                const ull ad3 = pack2(a4.w, a4.w);
                const float4 x4 = *reinterpret_cast<const float4*>(&Xc[q * 68 + tc * 4]);
                const ull xq0 = pack2(x4.x, x4.y);
                const ull xq1 = pack2(x4.z, x4.w);
                acc2[0][0] = fma2(ad0, xq0, acc2[0][0]);
                acc2[0][1] = fma2(ad0, xq1, acc2[0][1]);
                acc2[1][0] = fma2(ad1, xq0, acc2[1][0]);
                acc2[1][1] = fma2(ad1, xq1, acc2[1][1]);
                acc2[2][0] = fma2(ad2, xq0, acc2[2][0]);
                acc2[2][1] = fma2(ad2, xq1, acc2[2][1]);
                acc2[3][0] = fma2(ad3, xq0, acc2[3][0]);
                acc2[3][1] = fma2(ad3, xq1, acc2[3][1]);
            }
            if (it + 1 < 8) {
                float* An = As + ((it + 1) & 1) * 1088;
                float* Xn = Xs + ((it + 1) & 1) * 1088;
#pragma unroll
                for (int r = 0; r < 4; r++) {
                    const int rw = row + r * 16;
                    An[nn * 68 + rw] = aR[r];
                    Xn[nn * 68 + rw] = xR[r];
                }
            }
        }

        float* P = g_part + ((size_t)ns * BB + b) * KK * CC;
#pragma unroll
        for (int i = 0; i < 4; i++) {
            const float2 v0 = unpack2(acc2[i][0]);
            const float2 v1 = unpack2(acc2[i][1]);
            float4 o4 = make_float4(v0.x, v0.y, v1.x, v1.y);
            *reinterpret_cast<float4*>(&P[(size_t)(tk * 4 + i) * CC + c0 + tc * 4]) = o4;
        }
    }
    grid_bar();

    // ========== Phase D: epilogue, one (b,k) row per block ==========
    {
        float* redw = (float*)SMEM;       // 2
        float* red = redw + 2;            // 8
        float* rfs = red + 8;             // 1
        const int b = blk >> 6, k = blk & 63;

        // all independent loads first
        float wv = 0.f;
        if (tid < 64) wv = g_wpart[(b * 64 + tid) * KK + k];
        const int c = tid * 2;
        const size_t base = (size_t)b * KK * CC + (size_t)k * CC + c;
        float2 p[8];
#pragma unroll
        for (int nsp = 0; nsp < 8; nsp++)
            p[nsp] = *reinterpret_cast<const float2*>(&g_part[(size_t)nsp * BB * KK * CC + base]);
        const float2 a = *reinterpret_cast<const float2*>(&anchor[k * CC + c]);
        const float2 iv = *reinterpret_cast<const float2*>(&g_inv[k * CC + c]);

        if (tid < 64) {
#pragma unroll
            for (int o = 16; o > 0; o >>= 1) wv += __shfl_xor_sync(0xffffffffu, wv, o);
            if ((tid & 31) == 0) redw[tid >> 5] = wv;
        }
        __syncthreads();
        const float w = redw[0] + redw[1];
        const float invden = 1.f / (w + 1e-7f);

        float2 s = p[0];
#pragma unroll
        for (int nsp = 1; nsp < 8; nsp++) { s.x += p[nsp].x; s.y += p[nsp].y; }
        float2 v;
        v.x = (s.x - w * a.x) * iv.x * invden;
        v.y = (s.y - w * a.y) * iv.y * invden;

        float ss = v.x * v.x + v.y * v.y;
#pragma unroll
        for (int o = 16; o > 0; o >>= 1) ss += __shfl_xor_sync(0xffffffffu, ss, o);
        if ((tid & 31) == 0) red[tid >> 5] = ss;
        __syncthreads();
        if (tid == 0) {
            float sumsq = 0.f;
#pragma unroll
            for (int q = 0; q < 8; q++) sumsq += red[q];
            rfs[0] = 0.125f / fmaxf(sqrtf(sumsq), 1e-12f);  // row norm * 1/sqrt(K)
        }
        __syncthreads();
        const float rf = rfs[0];
        float2 o2;
        o2.x = v.x * rf; o2.y = v.y * rf;
        *reinterpret_cast<float2*>(&nodes_out[((size_t)b * KK + k) * CC + c]) = o2;
    }
}

// ------------------------------------------------------------------
extern "C" void kernel_launch(void* const* d_in, const int* in_sizes, int n_in,
                              void* d_out, int out_size) {
    (void)in_sizes; (void)n_in; (void)out_size;
    const float* x = (const float*)d_in[0];       // (4,512,32,32)
    const float* anchor = (const float*)d_in[1];  // (64,512)
    const float* sp = (const float*)d_in[2];      // (64,512)
    float* out = (float*)d_out;
    float* nodes_out = out;                        // B*K*C (viewed (B,C,K))
    float* soft_out = out + (size_t)BB * KK * CC;  // B*K*N

    fused_all<<<GRID, 256>>>(x, anchor, sp, nodes_out, soft_out);
}

// round 10
// speedup vs baseline: 1.1731x; 1.1731x over previous
#include <cuda_runtime.h>
#include <cstdint>

#define BB 4
#define CC 512
#define KK 64
#define NN 1024
#define NT 16      // d2 phase n-tile
#define GRID_A 256
#define GRID_B 128

typedef unsigned long long ull;

// ---- scratch (static __device__, no allocations) ----
__device__ __align__(16) float g_inv[KK * CC];    // [k][c]
__device__ __align__(16) float g_inv2t[CC * KK];  // [c][k]
__device__ __align__(16) float g_m2t[CC * KK];    // [c][k]
__device__ __align__(16) float g_ck[KK];
__device__ __align__(16) float g_wpart[(NN / NT) * BB * KK];  // [(nb*BB+b)*KK+k]
__device__ __align__(16) float g_part[4 * BB * KK * CC];      // 4 n-splits

// barrier state (monotonic gen -> graph-replay safe)
__device__ unsigned g_cntA[4] = {0, 0, 0, 0};
__device__ unsigned g_masterA = 0;
__device__ unsigned g_genA = 0;
__device__ unsigned g_cntB[4] = {0, 0, 0, 0};
__device__ unsigned g_masterB = 0;
__device__ unsigned g_genB = 0;

// ---- f32x2 helpers ----
__device__ __forceinline__ ull pack2(float x, float y) {
    ull r; asm("mov.b64 %0, {%1,%2};" : "=l"(r) : "f"(x), "f"(y)); return r;
}
__device__ __forceinline__ ull fma2(ull a, ull b, ull c) {
    ull d; asm("fma.rn.f32x2 %0, %1, %2, %3;" : "=l"(d) : "l"(a), "l"(b), "l"(c)); return d;
}
__device__ __forceinline__ float2 unpack2(ull v) {
    float2 f; asm("mov.b64 {%0,%1}, %2;" : "=f"(f.x), "=f"(f.y) : "l"(v)); return f;
}

// ---- cp.async helpers ----
__device__ __forceinline__ void cp_async16(void* smem_dst, const void* gsrc) {
    unsigned sa = (unsigned)__cvta_generic_to_shared(smem_dst);
    asm volatile("cp.async.cg.shared.global [%0], [%1], 16;\n" :: "r"(sa), "l"(gsrc));
}
__device__ __forceinline__ void cp_commit() { asm volatile("cp.async.commit_group;\n"); }
template <int N>
__device__ __forceinline__ void cp_wait() { asm volatile("cp.async.wait_group %0;\n" :: "n"(N)); }

// ---- spread grid barrier: 4 sub-counters + master ----
__device__ __forceinline__ void grid_bar(unsigned* cnt, unsigned* master,
                                         unsigned* gen, int sub_target, int blk) {
    __syncthreads();
    if (threadIdx.x == 0) {
        const unsigned g0 = *(volatile unsigned*)gen;
        __threadfence();
        const int sub = blk & 3;
        if (atomicAdd(&cnt[sub], 1u) == (unsigned)(sub_target - 1)) {
            cnt[sub] = 0;
            __threadfence();
            if (atomicAdd(master, 1u) == 3u) {
                *master = 0;
                __threadfence();
                atomicAdd(gen, 1u);
            }
        }
        while (*(volatile unsigned*)gen == g0) { __nanosleep(20); }
        __threadfence();
    }
    __syncthreads();
}

// ==================================================================
// Kernel A: [prep | d2 GEMM + softmax]
// grid 256 x 128 threads, 2 CTA/SM -> all co-resident.
// ==================================================================
__global__ __launch_bounds__(128, 2) void kernelA(const float* __restrict__ x,
                                                  const float* __restrict__ anchor,
                                                  const float* __restrict__ sp,
                                                  float* __restrict__ soft_out) {
    __shared__ __align__(16) float Wis[2][16 * 64];
    __shared__ __align__(16) float M2s[2][16 * 64];
    __shared__ __align__(16) float Xs[2][16 * NT];
    __shared__ float S[64 * 17];

    const int tid = threadIdx.x;
    const int blk = blockIdx.x;

    // ---- Phase 1: prep (blocks 0..63, one k-row each) ----
    if (blk < 64) {
        const int k = blk;
        float cks = 0.f;
#pragma unroll
        for (int r = 0; r < 4; r++) {
            const int c = tid + r * 128;
            const int gi = k * CC + c;
            const float s = 1.f / (1.f + __expf(-sp[gi]));
            const float inv = __fdividef(1.f, s + 1e-7f);
            const float inv2 = inv * inv;
            const float a = anchor[gi];
            g_inv[gi] = inv;
            g_inv2t[c * KK + k] = inv2;
            g_m2t[c * KK + k] = -2.f * a * inv2;
            cks += a * a * inv2;
        }
#pragma unroll
        for (int o = 16; o > 0; o >>= 1) cks += __shfl_xor_sync(0xffffffffu, cks, o);
        if ((tid & 31) == 0) S[tid >> 5] = cks;
        __syncthreads();
        if (tid == 0) g_ck[k] = S[0] + S[1] + S[2] + S[3];
    }
    grid_bar(g_cntA, &g_masterA, &g_genA, GRID_A / 4, blk);

    // ---- Phase 2: d2 GEMM (64k x 16n) + softmax (R5 k2 body) ----
    {
        const int nb = blk & 63;
        const int b = blk >> 6;
        const int n0 = nb * NT;
        const int tk = tid >> 3;  // 0..15 -> k base tk*4
        const int tn = tid & 7;   // 0..7  -> n base tn*2
        const float* xb = x + (size_t)b * CC * NN;

        auto issue = [&](int chunk, int buf) {
            const int c0 = chunk * 16;
#pragma unroll
            for (int r = 0; r < 2; r++) {
                const int idx = tid + r * 128;
                cp_async16(&Wis[buf][idx * 4], g_inv2t + c0 * KK + idx * 4);
                cp_async16(&M2s[buf][idx * 4], g_m2t + c0 * KK + idx * 4);
            }
            if (tid < 64) {
                const int cc = tid >> 2, nn4 = (tid & 3) * 4;
                cp_async16(&Xs[buf][cc * NT + nn4], xb + (size_t)(c0 + cc) * NN + n0 + nn4);
            }
            cp_commit();
        };

        ull acc[2][2];
#pragma unroll
        for (int i = 0; i < 2; i++)
#pragma unroll
            for (int j = 0; j < 2; j++) acc[i][j] = 0ull;

        issue(0, 0);
        for (int ch = 0; ch < 32; ch++) {
            if (ch + 1 < 32) { issue(ch + 1, (ch + 1) & 1); cp_wait<1>(); }
            else             { cp_wait<0>(); }
            __syncthreads();
            const float* Wb = Wis[ch & 1];
            const float* Mb = M2s[ch & 1];
            const float* Xb = Xs[ch & 1];
#pragma unroll
            for (int cc = 0; cc < 16; cc++) {
                const ulonglong2 wp = *reinterpret_cast<const ulonglong2*>(Wb + cc * 64 + tk * 4);
                const ulonglong2 mp = *reinterpret_cast<const ulonglong2*>(Mb + cc * 64 + tk * 4);
                const float2 xv = *reinterpret_cast<const float2*>(Xb + cc * NT + tn * 2);
                const ull xd0 = pack2(xv.x, xv.x);
                const ull xd1 = pack2(xv.y, xv.y);
                ull t;
                t = fma2(wp.x, xd0, mp.x); acc[0][0] = fma2(t, xd0, acc[0][0]);
                t = fma2(wp.x, xd1, mp.x); acc[0][1] = fma2(t, xd1, acc[0][1]);
                t = fma2(wp.y, xd0, mp.y); acc[1][0] = fma2(t, xd0, acc[1][0]);
                t = fma2(wp.y, xd1, mp.y); acc[1][1] = fma2(t, xd1, acc[1][1]);
            }
            __syncthreads();
        }

        // logits -> S (pad 17)
        {
            const int k0 = tk * 4;
#pragma unroll
            for (int kp = 0; kp < 2; kp++)
#pragma unroll
                for (int j = 0; j < 2; j++) {
                    const float2 v = unpack2(acc[kp][j]);
                    const int kk = k0 + kp * 2;
                    const int n = tn * 2 + j;
                    S[kk * 17 + n] = -0.5f * (v.x + g_ck[kk]);
                    S[(kk + 1) * 17 + n] = -0.5f * (v.y + g_ck[kk + 1]);
                }
        }
        __syncthreads();

        // serial softmax per column (threads 0..15) — proven shape
        if (tid < NT) {
            const int n = tid;
            float m = -1e30f;
#pragma unroll
            for (int k = 0; k < KK; k++) m = fmaxf(m, S[k * 17 + n]);
            float s = 0.f;
#pragma unroll
            for (int k = 0; k < KK; k++) s += __expf(S[k * 17 + n] - m);
            const float invs = 1.f / s;
            float* outp = soft_out + (size_t)b * KK * NN + n0 + n;
#pragma unroll
            for (int k = 0; k < KK; k++) {
                const float p = __expf(S[k * 17 + n] - m) * invs;
                S[k * 17 + n] = p;
                outp[(size_t)k * NN] = p;
            }
        }
        __syncthreads();

        // per-block wsum partials (threads 0..63)
        if (tid < 64) {
            float s = 0.f;
#pragma unroll
            for (int n = 0; n < NT; n++) s += S[tid * 17 + n];
            g_wpart[(nb * BB + b) * KK + tid] = s;
        }
    }
}

// ==================================================================
// Kernel B: [num GEMM | epilogue]
// grid 128 x 256 threads (1 CTA/SM, all co-resident).
// ==================================================================
__global__ __launch_bounds__(256) void kernelB(const float* __restrict__ x,
                                               const float* __restrict__ anchor,
                                               const float* __restrict__ soft,
                                               float* __restrict__ nodes_out) {
    __shared__ __align__(16) float As[16 * 68];
    __shared__ __align__(16) float Xs[16 * 68];
    __shared__ float redw[4];
    __shared__ float red[8];
    __shared__ float rfs[2];

    const int tid = threadIdx.x;
    const int blk = blockIdx.x;

    // ---- Phase 1: num GEMM (R5 k3 body), 128 items (8c x 4b x 4ns) ----
    {
        const int ct = blk & 7;
        const int b = (blk >> 3) & 3;
        const int ns = blk >> 5;
        const int c0 = ct * 64;
        const int nbeg = ns * (NN / 4);
        const int tc = tid & 15;
        const int tk = tid >> 4;

        ull acc2[4][2];
#pragma unroll
        for (int i = 0; i < 4; i++) { acc2[i][0] = 0ull; acc2[i][1] = 0ull; }

        const float* Ab = soft + (size_t)b * KK * NN;
        const float* xb = x + (size_t)b * CC * NN;

        for (int n0 = nbeg; n0 < nbeg + NN / 4; n0 += 16) {
#pragma unroll
            for (int r = 0; r < 4; r++) {
                const int idx = tid + r * 256;
                const int row = idx >> 4;
                const int nn = idx & 15;
                As[nn * 68 + row] = Ab[(size_t)row * NN + n0 + nn];
                Xs[nn * 68 + row] = xb[(size_t)(c0 + row) * NN + n0 + nn];
            }
            __syncthreads();
#pragma unroll
            for (int nn = 0; nn < 16; nn++) {
                const float4 a4 = *reinterpret_cast<const float4*>(&As[nn * 68 + tk * 4]);
                const ull ad0 = pack2(a4.x, a4.x);
                const ull ad1 = pack2(a4.y, a4.y);
                const ull ad2 = pack2(a4.z, a4.z);
                const ull ad3 = pack2(a4.w, a4.w);
                const float4 x4 = *reinterpret_cast<const float4*>(&Xs[nn * 68 + tc * 4]);
                const ull xq0 = pack2(x4.x, x4.y);
                const ull xq1 = pack2(x4.z, x4.w);
                acc2[0][0] = fma2(ad0, xq0, acc2[0][0]);
                acc2[0][1] = fma2(ad0, xq1, acc2[0][1]);
                acc2[1][0] = fma2(ad1, xq0, acc2[1][0]);
                acc2[1][1] = fma2(ad1, xq1, acc2[1][1]);
                acc2[2][0] = fma2(ad2, xq0, acc2[2][0]);
                acc2[2][1] = fma2(ad2, xq1, acc2[2][1]);
                acc2[3][0] = fma2(ad3, xq0, acc2[3][0]);
                acc2[3][1] = fma2(ad3, xq1, acc2[3][1]);
            }
            __syncthreads();
        }

        float* P = g_part + ((size_t)ns * BB + b) * KK * CC;
#pragma unroll
        for (int i = 0; i < 4; i++) {
            const float2 v0 = unpack2(acc2[i][0]);
            const float2 v1 = unpack2(acc2[i][1]);
            float4 o4 = make_float4(v0.x, v0.y, v1.x, v1.y);
            *reinterpret_cast<float4*>(&P[(size_t)(tk * 4 + i) * CC + c0 + tc * 4]) = o4;
        }
    }
    grid_bar(g_cntB, &g_masterB, &g_genB, GRID_B / 4, blk);

    // ---- Phase 2: epilogue, 2 (b,k) rows per block ----
    {
        const int h = tid >> 7;    // half 0/1
        const int ht = tid & 127;
        const int r = blk * 2 + h; // 0..255
        const int b = r >> 6, k = r & 63;

        // all independent loads first (max MLP)
        float wv = 0.f;
        if (ht < 64) wv = g_wpart[(ht * BB + b) * KK + k];
        const int c = ht * 4;
        const size_t base = (size_t)b * KK * CC + (size_t)k * CC + c;
        float4 p0 = *reinterpret_cast<const float4*>(&g_part[(size_t)0 * BB * KK * CC + base]);
        float4 p1 = *reinterpret_cast<const float4*>(&g_part[(size_t)1 * BB * KK * CC + base]);
        float4 p2 = *reinterpret_cast<const float4*>(&g_part[(size_t)2 * BB * KK * CC + base]);
        float4 p3 = *reinterpret_cast<const float4*>(&g_part[(size_t)3 * BB * KK * CC + base]);
        const float4 a = *reinterpret_cast<const float4*>(&anchor[k * CC + c]);
        const float4 iv = *reinterpret_cast<const float4*>(&g_inv[k * CC + c]);

        if (ht < 64) {
#pragma unroll
            for (int o = 16; o > 0; o >>= 1) wv += __shfl_xor_sync(0xffffffffu, wv, o);
            if ((ht & 31) == 0) redw[h * 2 + (ht >> 5)] = wv;
        }
        __syncthreads();
        const float w = redw[h * 2] + redw[h * 2 + 1];
        const float invden = 1.f / (w + 1e-7f);

        float4 s;
        s.x = (p0.x + p1.x) + (p2.x + p3.x);
        s.y = (p0.y + p1.y) + (p2.y + p3.y);
        s.z = (p0.z + p1.z) + (p2.z + p3.z);
        s.w = (p0.w + p1.w) + (p2.w + p3.w);
        float4 v;
        v.x = (s.x - w * a.x) * iv.x * invden;
        v.y = (s.y - w * a.y) * iv.y * invden;
        v.z = (s.z - w * a.z) * iv.z * invden;
        v.w = (s.w - w * a.w) * iv.w * invden;

        float ss = v.x * v.x + v.y * v.y + v.z * v.z + v.w * v.w;
#pragma unroll
        for (int o = 16; o > 0; o >>= 1) ss += __shfl_xor_sync(0xffffffffu, ss, o);
        if ((ht & 31) == 0) red[h * 4 + (ht >> 5)] = ss;
        __syncthreads();
        if (ht == 0) {
            const float sumsq = red[h * 4] + red[h * 4 + 1] + red[h * 4 + 2] + red[h * 4 + 3];
            rfs[h] = 0.125f / fmaxf(sqrtf(sumsq), 1e-12f);  // row norm * 1/sqrt(K)
        }
        __syncthreads();
        const float rf = rfs[h];
        float4 o4;
        o4.x = v.x * rf; o4.y = v.y * rf; o4.z = v.z * rf; o4.w = v.w * rf;
        *reinterpret_cast<float4*>(&nodes_out[((size_t)b * KK + k) * CC + c]) = o4;
    }
}

// ------------------------------------------------------------------
extern "C" void kernel_launch(void* const* d_in, const int* in_sizes, int n_in,
                              void* d_out, int out_size) {
    (void)in_sizes; (void)n_in; (void)out_size;
    const float* x = (const float*)d_in[0];       // (4,512,32,32)
    const float* anchor = (const float*)d_in[1];  // (64,512)
    const float* sp = (const float*)d_in[2];      // (64,512)
    float* out = (float*)d_out;
    float* nodes_out = out;                        // B*K*C (viewed (B,C,K))
    float* soft_out = out + (size_t)BB * KK * CC;  // B*K*N

    kernelA<<<GRID_A, 128>>>(x, anchor, sp, soft_out);
    kernelB<<<GRID_B, 256>>>(x, anchor, soft_out, nodes_out);
}

// round 11
// speedup vs baseline: 1.2540x; 1.0689x over previous
#include <cuda_runtime.h>
#include <cstdint>

#define BB 4
#define CC 512
#define KK 64
#define NN 1024
#define NT 32   // k2 n-tile

typedef unsigned long long ull;

// ---- scratch (static __device__, no allocations) ----
__device__ __align__(16) float g_inv[KK * CC];    // [k][c]
__device__ __align__(16) float g_inv2t[CC * KK];  // [c][k]
__device__ __align__(16) float g_m2t[CC * KK];    // [c][k]
__device__ __align__(16) float g_ck[KK];
__device__ __align__(16) float g_wpart[(NN / NT) * BB * KK];  // [(nb*BB+b)*KK+k]
__device__ __align__(16) float g_part[4 * BB * KK * CC];      // 4 n-splits

// ---- f32x2 helpers ----
__device__ __forceinline__ ull pack2(float x, float y) {
    ull r; asm("mov.b64 %0, {%1,%2};" : "=l"(r) : "f"(x), "f"(y)); return r;
}
__device__ __forceinline__ ull fma2(ull a, ull b, ull c) {
    ull d; asm("fma.rn.f32x2 %0, %1, %2, %3;" : "=l"(d) : "l"(a), "l"(b), "l"(c)); return d;
}
__device__ __forceinline__ float2 unpack2(ull v) {
    float2 f; asm("mov.b64 {%0,%1}, %2;" : "=f"(f.x), "=f"(f.y) : "l"(v)); return f;
}

// ---- cp.async helpers ----
__device__ __forceinline__ void cp_async16(void* smem_dst, const void* gsrc) {
    unsigned sa = (unsigned)__cvta_generic_to_shared(smem_dst);
    asm volatile("cp.async.cg.shared.global [%0], [%1], 16;\n" :: "r"(sa), "l"(gsrc));
}
__device__ __forceinline__ void cp_commit() { asm volatile("cp.async.commit_group;\n"); }
template <int N>
__device__ __forceinline__ void cp_wait() { asm volatile("cp.async.wait_group %0;\n" :: "n"(N)); }

// ------------------------------------------------------------------
// Kernel 1: precompute per-(k,c) quantities + per-k constant (proven R5)
// ------------------------------------------------------------------
__global__ __launch_bounds__(256) void k1_prep(const float* __restrict__ anchor,
                                               const float* __restrict__ sp) {
    const int k = blockIdx.x;
    const int tid = threadIdx.x;
    float cks = 0.f;
#pragma unroll
    for (int r = 0; r < CC / 256; r++) {
        const int c = tid + r * 256;
        const float s = 1.f / (1.f + __expf(-sp[k * CC + c]));
        const float inv = __fdividef(1.f, s + 1e-7f);
        const float inv2 = inv * inv;
        const float a = anchor[k * CC + c];
        g_inv[k * CC + c] = inv;
        g_inv2t[c * KK + k] = inv2;
        g_m2t[c * KK + k] = -2.f * a * inv2;
        cks += a * a * inv2;
    }
    __shared__ float red[8];
    float v = cks;
#pragma unroll
    for (int o = 16; o > 0; o >>= 1) v += __shfl_xor_sync(0xffffffffu, v, o);
    if ((tid & 31) == 0) red[tid >> 5] = v;
    __syncthreads();
    if (tid == 0) {
        float s = 0.f;
#pragma unroll
        for (int w = 0; w < 8; w++) s += red[w];
        g_ck[k] = s;
    }
}

// ------------------------------------------------------------------
// Kernel 2: d2 GEMM (64k x 32n, inner C=512) + fused softmax over K
// 256 threads, grid (NN/32, BB) = 128 blocks, 8 warps/CTA.
// Thread tile: 4k x 2n (proven R5 inner body). cp.async double-buffered.
// Halves the W/M L2 stream vs the 16n version.
// ------------------------------------------------------------------
__global__ __launch_bounds__(256) void k2_d2_softmax(const float* __restrict__ x,
                                                     float* __restrict__ soft_out) {
    const int b = blockIdx.y;
    const int nb = blockIdx.x;
    const int n0 = nb * NT;
    const int tid = threadIdx.x;
    const int tk = tid >> 4;  // 0..15 -> k base tk*4
    const int tn = tid & 15;  // 0..15 -> n base tn*2

    __shared__ __align__(16) float Wis[2][16 * 64];
    __shared__ __align__(16) float M2s[2][16 * 64];
    __shared__ __align__(16) float Xs[2][16 * NT];
    __shared__ float S[64 * 33];

    const float* xb = x + (size_t)b * CC * NN;

    auto issue = [&](int chunk, int buf) {
        const int c0 = chunk * 16;
        cp_async16(&Wis[buf][tid * 4], g_inv2t + c0 * KK + tid * 4);
        cp_async16(&M2s[buf][tid * 4], g_m2t + c0 * KK + tid * 4);
        if (tid < 128) {
            const int cc = tid >> 3, nn4 = (tid & 7) * 4;
            cp_async16(&Xs[buf][cc * NT + nn4], xb + (size_t)(c0 + cc) * NN + n0 + nn4);
        }
        cp_commit();
    };

    ull acc[2][2];
#pragma unroll
    for (int i = 0; i < 2; i++)
#pragma unroll
        for (int j = 0; j < 2; j++) acc[i][j] = 0ull;

    issue(0, 0);
    for (int ch = 0; ch < 32; ch++) {
        if (ch + 1 < 32) { issue(ch + 1, (ch + 1) & 1); cp_wait<1>(); }
        else             { cp_wait<0>(); }
        __syncthreads();
        const float* Wb = Wis[ch & 1];
        const float* Mb = M2s[ch & 1];
        const float* Xb = Xs[ch & 1];
#pragma unroll
        for (int cc = 0; cc < 16; cc++) {
            const ulonglong2 wp = *reinterpret_cast<const ulonglong2*>(Wb + cc * 64 + tk * 4);
            const ulonglong2 mp = *reinterpret_cast<const ulonglong2*>(Mb + cc * 64 + tk * 4);
            const float2 xv = *reinterpret_cast<const float2*>(Xb + cc * NT + tn * 2);
            const ull xd0 = pack2(xv.x, xv.x);
            const ull xd1 = pack2(xv.y, xv.y);
            ull t;
            t = fma2(wp.x, xd0, mp.x); acc[0][0] = fma2(t, xd0, acc[0][0]);
            t = fma2(wp.x, xd1, mp.x); acc[0][1] = fma2(t, xd1, acc[0][1]);
            t = fma2(wp.y, xd0, mp.y); acc[1][0] = fma2(t, xd0, acc[1][0]);
            t = fma2(wp.y, xd1, mp.y); acc[1][1] = fma2(t, xd1, acc[1][1]);
        }
        __syncthreads();
    }

    // logits -> S (pad 33)
    {
        const int k0 = tk * 4;
#pragma unroll
        for (int kp = 0; kp < 2; kp++)
#pragma unroll
            for (int j = 0; j < 2; j++) {
                const float2 v = unpack2(acc[kp][j]);
                const int kk = k0 + kp * 2;
                const int n = tn * 2 + j;
                S[kk * 33 + n] = -0.5f * (v.x + g_ck[kk]);
                S[(kk + 1) * 33 + n] = -0.5f * (v.y + g_ck[kk + 1]);
            }
    }
    __syncthreads();

    // serial softmax per column (threads 0..31) — proven shape
    if (tid < NT) {
        const int n = tid;
        float m = -1e30f;
#pragma unroll
        for (int k = 0; k < KK; k++) m = fmaxf(m, S[k * 33 + n]);
        float s = 0.f;
#pragma unroll
        for (int k = 0; k < KK; k++) s += __expf(S[k * 33 + n] - m);
        const float invs = 1.f / s;
        float* outp = soft_out + (size_t)b * KK * NN + n0 + n;
#pragma unroll
        for (int k = 0; k < KK; k++) {
            const float p = __expf(S[k * 33 + n] - m) * invs;
            S[k * 33 + n] = p;
            outp[(size_t)k * NN] = p;
        }
    }
    __syncthreads();

    // per-block wsum partials (threads 0..63, one per k)
    if (tid < 64) {
        float s = 0.f;
#pragma unroll
        for (int n = 0; n < NT; n++) s += S[tid * 33 + n];
        g_wpart[(nb * BB + b) * KK + tid] = s;
    }
}

// ------------------------------------------------------------------
// Kernel 3: num[b,k,c] = sum_n A[b,k,n]*x[b,c,n], split-N=4 partials
// grid (16 c-tiles, BB, 4 ns) = 256 blocks -> ~2 CTAs/SM co-resident.
// 256 threads, 64k x 32c tile, thread 4k(2 packed pairs) x 2c.
// ------------------------------------------------------------------
__global__ __launch_bounds__(256) void k3_num(const float* __restrict__ soft,
                                              const float* __restrict__ x) {
    const int b = blockIdx.y;
    const int c0 = blockIdx.x * 32;
    const int ns = blockIdx.z;
    const int nbeg = ns * (NN / 4);

    __shared__ __align__(16) float As[16 * 68];  // [nn][k], pad 68
    __shared__ __align__(16) float Xs[16 * 36];  // [nn][c-local], pad 36

    const int tid = threadIdx.x;
    const int tc = tid & 15;   // c pair base = tc*2
    const int tk = tid >> 4;   // k base = tk*4 (two packed pairs)

    ull acc[2][2];  // [kp][cj]
#pragma unroll
    for (int i = 0; i < 2; i++) { acc[i][0] = 0ull; acc[i][1] = 0ull; }

    const float* Ab = soft + (size_t)b * KK * NN;
    const float* xb = x + (size_t)b * CC * NN;

    for (int n0 = nbeg; n0 < nbeg + NN / 4; n0 += 16) {
#pragma unroll
        for (int r = 0; r < 4; r++) {
            const int idx = tid + r * 256;  // 0..1023
            const int row = idx >> 4;       // 0..63 (k)
            const int nn = idx & 15;
            As[nn * 68 + row] = Ab[(size_t)row * NN + n0 + nn];
        }
#pragma unroll
        for (int r = 0; r < 2; r++) {
            const int idx = tid + r * 256;  // 0..511
            const int row = idx >> 4;       // 0..31 (c-local)
            const int nn = idx & 15;
            Xs[nn * 36 + row] = xb[(size_t)(c0 + row) * NN + n0 + nn];
        }
        __syncthreads();
#pragma unroll
        for (int nn = 0; nn < 16; nn++) {
            const ulonglong2 ap = *reinterpret_cast<const ulonglong2*>(&As[nn * 68 + tk * 4]);
            const float2 xv = *reinterpret_cast<const float2*>(&Xs[nn * 36 + tc * 2]);
            const ull xd0 = pack2(xv.x, xv.x);
            const ull xd1 = pack2(xv.y, xv.y);
            acc[0][0] = fma2(ap.x, xd0, acc[0][0]);
            acc[0][1] = fma2(ap.x, xd1, acc[0][1]);
            acc[1][0] = fma2(ap.y, xd0, acc[1][0]);
            acc[1][1] = fma2(ap.y, xd1, acc[1][1]);
        }
        __syncthreads();
    }

    float* P = g_part + ((size_t)ns * BB + b) * KK * CC;
#pragma unroll
    for (int kp = 0; kp < 2; kp++)
#pragma unroll
        for (int cj = 0; cj < 2; cj++) {
            const float2 v = unpack2(acc[kp][cj]);  // (k, k+1) for one c
            const int kg = tk * 4 + kp * 2;
            const int cg = c0 + tc * 2 + cj;
            P[(size_t)kg * CC + cg] = v.x;
            P[(size_t)(kg + 1) * CC + cg] = v.y;
        }
}

// ------------------------------------------------------------------
// Kernel 4: epilogue per (b,k): combine partials, subtract, scale,
// row-normalize, exact flat factor 1/8. (proven R5/R7 body)
// ------------------------------------------------------------------
__global__ __launch_bounds__(128) void k4_nodes(const float* __restrict__ anchor,
                                                float* __restrict__ nodes_out) {
    const int k = blockIdx.x;
    const int b = blockIdx.y;
    const int tid = threadIdx.x;

    __shared__ float redw[1];
    __shared__ float red[4];
    __shared__ float rfs;

    // issue ALL independent loads first (max MLP)
    float wv = 0.f;
    if (tid < 32) wv = g_wpart[(tid * BB + b) * KK + k];
    const int c = tid * 4;
    float4 p0 = *reinterpret_cast<const float4*>(&g_part[((size_t)0 * BB + b) * KK * CC + (size_t)k * CC + c]);
    float4 p1 = *reinterpret_cast<const float4*>(&g_part[((size_t)1 * BB + b) * KK * CC + (size_t)k * CC + c]);
    float4 p2 = *reinterpret_cast<const float4*>(&g_part[((size_t)2 * BB + b) * KK * CC + (size_t)k * CC + c]);
    float4 p3 = *reinterpret_cast<const float4*>(&g_part[((size_t)3 * BB + b) * KK * CC + (size_t)k * CC + c]);
    const float4 a = *reinterpret_cast<const float4*>(&anchor[k * CC + c]);
    const float4 iv = *reinterpret_cast<const float4*>(&g_inv[k * CC + c]);

    if (tid < 32) {
#pragma unroll
        for (int o = 16; o > 0; o >>= 1) wv += __shfl_xor_sync(0xffffffffu, wv, o);
        if (tid == 0) redw[0] = wv;
    }
    __syncthreads();
    const float w = redw[0];
    const float invden = 1.f / (w + 1e-7f);

    float4 s;
    s.x = (p0.x + p1.x) + (p2.x + p3.x);
    s.y = (p0.y + p1.y) + (p2.y + p3.y);
    s.z = (p0.z + p1.z) + (p2.z + p3.z);
    s.w = (p0.w + p1.w) + (p2.w + p3.w);
    float4 v;
    v.x = (s.x - w * a.x) * iv.x * invden;
    v.y = (s.y - w * a.y) * iv.y * invden;
    v.z = (s.z - w * a.z) * iv.z * invden;
    v.w = (s.w - w * a.w) * iv.w * invden;

    float ss = v.x * v.x + v.y * v.y + v.z * v.z + v.w * v.w;
#pragma unroll
    for (int o = 16; o > 0; o >>= 1) ss += __shfl_xor_sync(0xffffffffu, ss, o);
    if ((tid & 31) == 0) red[tid >> 5] = ss;
    __syncthreads();
    if (tid == 0) {
        const float sumsq = red[0] + red[1] + red[2] + red[3];
        rfs = 0.125f / fmaxf(sqrtf(sumsq), 1e-12f);  // row norm * 1/sqrt(K)
    }
    __syncthreads();
    const float rf = rfs;
    float4 o4;
    o4.x = v.x * rf; o4.y = v.y * rf; o4.z = v.z * rf; o4.w = v.w * rf;
    *reinterpret_cast<float4*>(&nodes_out[((size_t)b * KK + k) * CC + c]) = o4;
}

// ------------------------------------------------------------------
extern "C" void kernel_launch(void* const* d_in, const int* in_sizes, int n_in,
                              void* d_out, int out_size) {
    (void)in_sizes; (void)n_in; (void)out_size;
    const float* x = (const float*)d_in[0];       // (4,512,32,32)
    const float* anchor = (const float*)d_in[1];  // (64,512)
    const float* sp = (const float*)d_in[2];      // (64,512)
    float* out = (float*)d_out;
    float* nodes_out = out;                        // B*K*C (viewed (B,C,K))
    float* soft_out = out + (size_t)BB * KK * CC;  // B*K*N

    k1_prep<<<KK, 256>>>(anchor, sp);
    k2_d2_softmax<<<dim3(NN / NT, BB), 256>>>(x, soft_out);
    k3_num<<<dim3(16, BB, 4), 256>>>(soft_out, x);
    k4_nodes<<<dim3(KK, BB), 128>>>(anchor, nodes_out);
}

// round 12
// speedup vs baseline: 1.2848x; 1.0245x over previous
#include <cuda_runtime.h>
#include <cstdint>

#define BB 4
#define CC 512
#define KK 64
#define NN 1024
#define NT 32   // k2 n-tile

typedef unsigned long long ull;

// ---- scratch (static __device__, no allocations) ----
__device__ __align__(16) float g_inv[KK * CC];    // [k][c]
__device__ __align__(16) float g_inv2t[CC * KK];  // [c][k]
__device__ __align__(16) float g_m2t[CC * KK];    // [c][k]
__device__ __align__(16) float g_ck[KK];
__device__ __align__(16) float g_wpart[(NN / NT) * BB * KK];  // [(nb*BB+b)*KK+k]
__device__ __align__(16) float g_part[4 * BB * KK * CC];      // 4 n-splits

// ---- f32x2 helpers ----
__device__ __forceinline__ ull pack2(float x, float y) {
    ull r; asm("mov.b64 %0, {%1,%2};" : "=l"(r) : "f"(x), "f"(y)); return r;
}
__device__ __forceinline__ ull fma2(ull a, ull b, ull c) {
    ull d; asm("fma.rn.f32x2 %0, %1, %2, %3;" : "=l"(d) : "l"(a), "l"(b), "l"(c)); return d;
}
__device__ __forceinline__ float2 unpack2(ull v) {
    float2 f; asm("mov.b64 {%0,%1}, %2;" : "=f"(f.x), "=f"(f.y) : "l"(v)); return f;
}

// ---- cp.async helpers ----
__device__ __forceinline__ void cp_async16(void* smem_dst, const void* gsrc) {
    unsigned sa = (unsigned)__cvta_generic_to_shared(smem_dst);
    asm volatile("cp.async.cg.shared.global [%0], [%1], 16;\n" :: "r"(sa), "l"(gsrc));
}
__device__ __forceinline__ void cp_commit() { asm volatile("cp.async.commit_group;\n"); }
template <int N>
__device__ __forceinline__ void cp_wait() { asm volatile("cp.async.wait_group %0;\n" :: "n"(N)); }

// ------------------------------------------------------------------
// Kernel 1: precompute per-(k,c) quantities + per-k constant (proven)
// ------------------------------------------------------------------
__global__ __launch_bounds__(256) void k1_prep(const float* __restrict__ anchor,
                                               const float* __restrict__ sp) {
    const int k = blockIdx.x;
    const int tid = threadIdx.x;
    float cks = 0.f;
#pragma unroll
    for (int r = 0; r < CC / 256; r++) {
        const int c = tid + r * 256;
        const float s = 1.f / (1.f + __expf(-sp[k * CC + c]));
        const float inv = __fdividef(1.f, s + 1e-7f);
        const float inv2 = inv * inv;
        const float a = anchor[k * CC + c];
        g_inv[k * CC + c] = inv;
        g_inv2t[c * KK + k] = inv2;
        g_m2t[c * KK + k] = -2.f * a * inv2;
        cks += a * a * inv2;
    }
    __shared__ float red[8];
    float v = cks;
#pragma unroll
    for (int o = 16; o > 0; o >>= 1) v += __shfl_xor_sync(0xffffffffu, v, o);
    if ((tid & 31) == 0) red[tid >> 5] = v;
    __syncthreads();
    if (tid == 0) {
        float s = 0.f;
#pragma unroll
        for (int w = 0; w < 8; w++) s += red[w];
        g_ck[k] = s;
    }
}

// ------------------------------------------------------------------
// Kernel 2: d2 GEMM (64k x 32n, inner C=512) + fused softmax over K
// 256 threads, grid (NN/32, BB) = 128 blocks. Thread tile 4k x 2n.
// 3-buffer cp.async ring, ONE __syncthreads per chunk.
// ------------------------------------------------------------------
__global__ __launch_bounds__(256) void k2_d2_softmax(const float* __restrict__ x,
                                                     float* __restrict__ soft_out) {
    const int b = blockIdx.y;
    const int nb = blockIdx.x;
    const int n0 = nb * NT;
    const int tid = threadIdx.x;
    const int tk = tid >> 4;  // 0..15 -> k base tk*4
    const int tn = tid & 15;  // 0..15 -> n base tn*2

    __shared__ __align__(16) float Wis[3][16 * 64];
    __shared__ __align__(16) float M2s[3][16 * 64];
    __shared__ __align__(16) float Xs[3][16 * NT];
    __shared__ float S[64 * 33];

    const float* xb = x + (size_t)b * CC * NN;

    auto issue = [&](int chunk, int buf) {
        const int c0 = chunk * 16;
        cp_async16(&Wis[buf][tid * 4], g_inv2t + c0 * KK + tid * 4);
        cp_async16(&M2s[buf][tid * 4], g_m2t + c0 * KK + tid * 4);
        if (tid < 128) {
            const int cc = tid >> 3, nn4 = (tid & 7) * 4;
            cp_async16(&Xs[buf][cc * NT + nn4], xb + (size_t)(c0 + cc) * NN + n0 + nn4);
        }
        cp_commit();
    };

    ull acc[2][2];
#pragma unroll
    for (int i = 0; i < 2; i++)
#pragma unroll
        for (int j = 0; j < 2; j++) acc[i][j] = 0ull;

    issue(0, 0);
    issue(1, 1);
    for (int ch = 0; ch < 32; ch++) {
        cp_wait<1>();
        __syncthreads();
        const int buf = ch - (ch / 3) * 3;  // ch % 3
        const float* Wb = Wis[buf];
        const float* Mb = M2s[buf];
        const float* Xb = Xs[buf];
#pragma unroll
        for (int cc = 0; cc < 16; cc++) {
            const ulonglong2 wp = *reinterpret_cast<const ulonglong2*>(Wb + cc * 64 + tk * 4);
            const ulonglong2 mp = *reinterpret_cast<const ulonglong2*>(Mb + cc * 64 + tk * 4);
            const float2 xv = *reinterpret_cast<const float2*>(Xb + cc * NT + tn * 2);
            const ull xd0 = pack2(xv.x, xv.x);
            const ull xd1 = pack2(xv.y, xv.y);
            ull t;
            t = fma2(wp.x, xd0, mp.x); acc[0][0] = fma2(t, xd0, acc[0][0]);
            t = fma2(wp.x, xd1, mp.x); acc[0][1] = fma2(t, xd1, acc[0][1]);
            t = fma2(wp.y, xd0, mp.y); acc[1][0] = fma2(t, xd0, acc[1][0]);
            t = fma2(wp.y, xd1, mp.y); acc[1][1] = fma2(t, xd1, acc[1][1]);
        }
        if (ch + 2 < 32) {
            const int nb2 = (ch + 2) - ((ch + 2) / 3) * 3;
            issue(ch + 2, nb2);
        }
    }

    // logits -> S (pad 33)
    {
        const int k0 = tk * 4;
#pragma unroll
        for (int kp = 0; kp < 2; kp++)
#pragma unroll
            for (int j = 0; j < 2; j++) {
                const float2 v = unpack2(acc[kp][j]);
                const int kk = k0 + kp * 2;
                const int n = tn * 2 + j;
                S[kk * 33 + n] = -0.5f * (v.x + g_ck[kk]);
                S[(kk + 1) * 33 + n] = -0.5f * (v.y + g_ck[kk + 1]);
            }
    }
    __syncthreads();

    // serial softmax per column (threads 0..31) — proven shape
    if (tid < NT) {
        const int n = tid;
        float m = -1e30f;
#pragma unroll
        for (int k = 0; k < KK; k++) m = fmaxf(m, S[k * 33 + n]);
        float s = 0.f;
#pragma unroll
        for (int k = 0; k < KK; k++) s += __expf(S[k * 33 + n] - m);
        const float invs = 1.f / s;
        float* outp = soft_out + (size_t)b * KK * NN + n0 + n;
#pragma unroll
        for (int k = 0; k < KK; k++) {
            const float p = __expf(S[k * 33 + n] - m) * invs;
            S[k * 33 + n] = p;
            outp[(size_t)k * NN] = p;
        }
    }
    __syncthreads();

    // per-block wsum partials (threads 0..63, one per k)
    if (tid < 64) {
        float s = 0.f;
#pragma unroll
        for (int n = 0; n < NT; n++) s += S[tid * 33 + n];
        g_wpart[(nb * BB + b) * KK + tid] = s;
    }
}

// ------------------------------------------------------------------
// Kernel 3: num[b,k,c] = sum_n A[b,k,n]*x[b,c,n], split-N=4 partials
// grid (16 c-tiles, BB, 4 ns) = 256 blocks, 256 threads.
// Register-prefetch double buffer: ONE __syncthreads per n-chunk.
// ------------------------------------------------------------------
__global__ __launch_bounds__(256) void k3_num(const float* __restrict__ soft,
                                              const float* __restrict__ x) {
    const int b = blockIdx.y;
    const int c0 = blockIdx.x * 32;
    const int ns = blockIdx.z;
    const int nbeg = ns * (NN / 4);

    __shared__ __align__(16) float As[2][16 * 68];  // [nn][k], pad 68
    __shared__ __align__(16) float Xs[2][16 * 36];  // [nn][c-local], pad 36

    const int tid = threadIdx.x;
    const int tc = tid & 15;   // c pair base = tc*2
    const int tk = tid >> 4;   // k base = tk*4 (two packed pairs)
    const int lrow = tid >> 4; // load row base (0..15)
    const int lnn = tid & 15;  // load nn

    ull acc[2][2];  // [kp][cj]
#pragma unroll
    for (int i = 0; i < 2; i++) { acc[i][0] = 0ull; acc[i][1] = 0ull; }

    const float* Ab = soft + (size_t)b * KK * NN;
    const float* xb = x + (size_t)b * CC * NN;

    // prologue: load + store iter 0 into buf 0
    {
        const int n0 = nbeg;
#pragma unroll
        for (int r = 0; r < 4; r++) {
            const int row = lrow + r * 16;  // 0..63 (k)
            As[0][lnn * 68 + row] = Ab[(size_t)row * NN + n0 + lnn];
        }
#pragma unroll
        for (int r = 0; r < 2; r++) {
            const int row = lrow + r * 16;  // 0..31 (c-local)
            Xs[0][lnn * 36 + row] = xb[(size_t)(c0 + row) * NN + n0 + lnn];
        }
    }

    for (int it = 0; it < 16; it++) {
        float aR[4], xR[2];
        const bool more = (it + 1 < 16);
        if (more) {
            const int n0 = nbeg + (it + 1) * 16;
#pragma unroll
            for (int r = 0; r < 4; r++)
                aR[r] = Ab[(size_t)(lrow + r * 16) * NN + n0 + lnn];
#pragma unroll
            for (int r = 0; r < 2; r++)
                xR[r] = xb[(size_t)(c0 + lrow + r * 16) * NN + n0 + lnn];
        }
        __syncthreads();
        const float* Ac = As[it & 1];
        const float* Xc = Xs[it & 1];
#pragma unroll
        for (int nn = 0; nn < 16; nn++) {
            const ulonglong2 ap = *reinterpret_cast<const ulonglong2*>(&Ac[nn * 68 + tk * 4]);
            const float2 xv = *reinterpret_cast<const float2*>(&Xc[nn * 36 + tc * 2]);
            const ull xd0 = pack2(xv.x, xv.x);
            const ull xd1 = pack2(xv.y, xv.y);
            acc[0][0] = fma2(ap.x, xd0, acc[0][0]);
            acc[0][1] = fma2(ap.x, xd1, acc[0][1]);
            acc[1][0] = fma2(ap.y, xd0, acc[1][0]);
            acc[1][1] = fma2(ap.y, xd1, acc[1][1]);
        }
        if (more) {
            float* An = As[(it + 1) & 1];
            float* Xn = Xs[(it + 1) & 1];
#pragma unroll
            for (int r = 0; r < 4; r++)
                An[lnn * 68 + lrow + r * 16] = aR[r];
#pragma unroll
            for (int r = 0; r < 2; r++)
                Xn[lnn * 36 + lrow + r * 16] = xR[r];
        }
    }

    float* P = g_part + ((size_t)ns * BB + b) * KK * CC;
#pragma unroll
    for (int kp = 0; kp < 2; kp++)
#pragma unroll
        for (int cj = 0; cj < 2; cj++) {
            const float2 v = unpack2(acc[kp][cj]);  // (k, k+1) for one c
            const int kg = tk * 4 + kp * 2;
            const int cg = c0 + tc * 2 + cj;
            P[(size_t)kg * CC + cg] = v.x;
            P[(size_t)(kg + 1) * CC + cg] = v.y;
        }
}

// ------------------------------------------------------------------
// Kernel 4: epilogue per (b,k): combine partials, subtract, scale,
// row-normalize, exact flat factor 1/8. (proven body)
// ------------------------------------------------------------------
__global__ __launch_bounds__(128) void k4_nodes(const float* __restrict__ anchor,
                                                float* __restrict__ nodes_out) {
    const int k = blockIdx.x;
    const int b = blockIdx.y;
    const int tid = threadIdx.x;

    __shared__ float redw[1];
    __shared__ float red[4];
    __shared__ float rfs;

    // issue ALL independent loads first (max MLP)
    float wv = 0.f;
    if (tid < 32) wv = g_wpart[(tid * BB + b) * KK + k];
    const int c = tid * 4;
    float4 p0 = *reinterpret_cast<const float4*>(&g_part[((size_t)0 * BB + b) * KK * CC + (size_t)k * CC + c]);
    float4 p1 = *reinterpret_cast<const float4*>(&g_part[((size_t)1 * BB + b) * KK * CC + (size_t)k * CC + c]);
    float4 p2 = *reinterpret_cast<const float4*>(&g_part[((size_t)2 * BB + b) * KK * CC + (size_t)k * CC + c]);
    float4 p3 = *reinterpret_cast<const float4*>(&g_part[((size_t)3 * BB + b) * KK * CC + (size_t)k * CC + c]);
    const float4 a = *reinterpret_cast<const float4*>(&anchor[k * CC + c]);
    const float4 iv = *reinterpret_cast<const float4*>(&g_inv[k * CC + c]);

    if (tid < 32) {
#pragma unroll
        for (int o = 16; o > 0; o >>= 1) wv += __shfl_xor_sync(0xffffffffu, wv, o);
        if (tid == 0) redw[0] = wv;
    }
    __syncthreads();
    const float w = redw[0];
    const float invden = 1.f / (w + 1e-7f);

    float4 s;
    s.x = (p0.x + p1.x) + (p2.x + p3.x);
    s.y = (p0.y + p1.y) + (p2.y + p3.y);
    s.z = (p0.z + p1.z) + (p2.z + p3.z);
    s.w = (p0.w + p1.w) + (p2.w + p3.w);
    float4 v;
    v.x = (s.x - w * a.x) * iv.x * invden;
    v.y = (s.y - w * a.y) * iv.y * invden;
    v.z = (s.z - w * a.z) * iv.z * invden;
    v.w = (s.w - w * a.w) * iv.w * invden;

    float ss = v.x * v.x + v.y * v.y + v.z * v.z + v.w * v.w;
#pragma unroll
    for (int o = 16; o > 0; o >>= 1) ss += __shfl_xor_sync(0xffffffffu, ss, o);
    if ((tid & 31) == 0) red[tid >> 5] = ss;
    __syncthreads();
    if (tid == 0) {
        const float sumsq = red[0] + red[1] + red[2] + red[3];
        rfs = 0.125f / fmaxf(sqrtf(sumsq), 1e-12f);  // row norm * 1/sqrt(K)
    }
    __syncthreads();
    const float rf = rfs;
    float4 o4;
    o4.x = v.x * rf; o4.y = v.y * rf; o4.z = v.z * rf; o4.w = v.w * rf;
    *reinterpret_cast<float4*>(&nodes_out[((size_t)b * KK + k) * CC + c]) = o4;
}

// ------------------------------------------------------------------
extern "C" void kernel_launch(void* const* d_in, const int* in_sizes, int n_in,
                              void* d_out, int out_size) {
    (void)in_sizes; (void)n_in; (void)out_size;
    const float* x = (const float*)d_in[0];       // (4,512,32,32)
    const float* anchor = (const float*)d_in[1];  // (64,512)
    const float* sp = (const float*)d_in[2];      // (64,512)
    float* out = (float*)d_out;
    float* nodes_out = out;                        // B*K*C (viewed (B,C,K))
    float* soft_out = out + (size_t)BB * KK * CC;  // B*K*N

    k1_prep<<<KK, 256>>>(anchor, sp);
    k2_d2_softmax<<<dim3(NN / NT, BB), 256>>>(x, soft_out);
    k3_num<<<dim3(16, BB, 4), 256>>>(soft_out, x);
    k4_nodes<<<dim3(KK, BB), 128>>>(anchor, nodes_out);
}